// round 4
// baseline (speedup 1.0000x reference)
#include <cuda_runtime.h>
#include <math.h>

#define Bsz 512
#define Tsz 512
#define FS 64
#define FC 32
#define H 256
#define LN_EPS 1e-5f

typedef unsigned long long ull;

// Weights packed k-major as float4 covering TWO k-rows:
//   g4[kp*H + j] = { m1[2kp, j], m2[2kp, j], m1[2kp+1, j], m2[2kp+1, j] }
__device__ float4 g4_s0[(FS / 2) * H];   // {Win0_seq, Wg0_seq}
__device__ float4 g4_c0[(FC / 2) * H];   // {Win0_ctx, Wg0_ctx}
__device__ float4 g4_h0[(H / 2) * H];    // {Wg0_h,    Wrec0}
__device__ float4 g4_x1[(H / 2) * H];    // {Win1,     Wg1_x}
__device__ float4 g4_h1[(H / 2) * H];    // {Wg1_h,    Wrec1}

__global__ void setup_kernel(const float* __restrict__ Win0,
                             const float* __restrict__ Wrec0,
                             const float* __restrict__ Wg0,
                             const float* __restrict__ Win1,
                             const float* __restrict__ Wrec1,
                             const float* __restrict__ Wg1) {
    int j  = threadIdx.x;
    int k2 = blockIdx.x;
    if (k2 < 32) {
        int k = 2 * k2;
        g4_s0[k2 * H + j] = make_float4(Win0[j * 96 + k],     Wg0[j * 352 + k],
                                        Win0[j * 96 + k + 1], Wg0[j * 352 + k + 1]);
    } else if (k2 < 48) {
        int kk = 2 * (k2 - 32);
        g4_c0[(k2 - 32) * H + j] =
            make_float4(Win0[j * 96 + 64 + kk],     Wg0[j * 352 + 64 + kk],
                        Win0[j * 96 + 64 + kk + 1], Wg0[j * 352 + 64 + kk + 1]);
    } else if (k2 < 176) {
        int kk = 2 * (k2 - 48);
        g4_h0[(k2 - 48) * H + j] =
            make_float4(Wg0[j * 352 + 96 + kk],     Wrec0[j * H + kk],
                        Wg0[j * 352 + 96 + kk + 1], Wrec0[j * H + kk + 1]);
    } else if (k2 < 304) {
        int kk = 2 * (k2 - 176);
        g4_x1[(k2 - 176) * H + j] =
            make_float4(Win1[j * H + kk],     Wg1[j * 512 + kk],
                        Win1[j * H + kk + 1], Wg1[j * 512 + kk + 1]);
    } else {
        int kk = 2 * (k2 - 304);
        g4_h1[(k2 - 304) * H + j] =
            make_float4(Wg1[j * 512 + 256 + kk],     Wrec1[j * H + kk],
                        Wg1[j * 512 + 256 + kk + 1], Wrec1[j * H + kk + 1]);
    }
}

// ---- packed fp32x2 helpers (bit-identical to 2x fma.rn.f32) ----
__device__ __forceinline__ ull pk2(float a, float b) {
    ull r; asm("mov.b64 %0,{%1,%2};" : "=l"(r) : "f"(a), "f"(b)); return r;
}
__device__ __forceinline__ void up2(ull v, float& a, float& b) {
    asm("mov.b64 {%0,%1},%2;" : "=f"(a), "=f"(b) : "l"(v));
}
__device__ __forceinline__ void fma2(ull& d, ull a, ull b) {
    asm("fma.rn.f32x2 %0,%1,%2,%0;" : "+l"(d) : "l"(a), "l"(b));
}

// ---- fast transcendentals (abs err ~1e-7 at the magnitudes that matter) ----
__device__ __forceinline__ float fast_tanh(float x) {
    float xc = fminf(fmaxf(x, -30.f), 30.f);
    float e  = __expf(2.f * xc);
    return __fdividef(e - 1.f, e + 1.f);
}
__device__ __forceinline__ float fast_sigmoid(float x) {
    return __fdividef(1.f, 1.f + __expf(-x));
}

// ---- 32-k-row blocks: preload (16x LDG.128) and compute (dual matvec) ----
__device__ __forceinline__ void pre32(float4 w[16], const float4* __restrict__ pk4,
                                      int kp, int j) {
#pragma unroll
    for (int i = 0; i < 16; i++) w[i] = pk4[(size_t)(kp + i) * H + j];
}

__device__ __forceinline__ void comp32(const float4 w[16], const ull* __restrict__ hhb,
                                       int kb,
                                       ull& a1_01, ull& a1_23, ull& a2_01, ull& a2_23) {
#pragma unroll
    for (int i = 0; i < 16; i++) {
        ulonglong2 hA = *(const ulonglong2*)(hhb + (size_t)(kb + 2 * i) * 2);
        ulonglong2 hB = *(const ulonglong2*)(hhb + (size_t)(kb + 2 * i + 1) * 2);
        ull wx0 = pk2(w[i].x, w[i].x), wy0 = pk2(w[i].y, w[i].y);
        fma2(a1_01, wx0, hA.x); fma2(a1_23, wx0, hA.y);
        fma2(a2_01, wy0, hA.x); fma2(a2_23, wy0, hA.y);
        ull wx1 = pk2(w[i].z, w[i].z), wy1 = pk2(w[i].w, w[i].w);
        fma2(a1_01, wx1, hB.x); fma2(a1_23, wx1, hB.y);
        fma2(a2_01, wy1, hB.x); fma2(a2_23, wy1, hB.y);
    }
}

// Dual matvec over K k-rows. On entry wA must hold pk4 rows 0..31 (preloaded by
// the PREVIOUS phase). On exit wA holds pknext rows 0..31 — the next phase's
// weights, issued a full compute-block + epilogue + barrier before their use.
template<int K>
__device__ __forceinline__ void matvecP(const float4* __restrict__ pk4,
                                        const float4* __restrict__ pknext,
                                        int j, const ull* __restrict__ hhb,
                                        float4 wA[16],
                                        ull& a1_01, ull& a1_23, ull& a2_01, ull& a2_23) {
    float4 wB[16];
#pragma unroll 1
    for (int kb = 0; kb < K; kb += 64) {
        pre32(wB, pk4, (kb + 32) >> 1, j);
        comp32(wA, hhb, kb, a1_01, a1_23, a2_01, a2_23);
        if (kb + 64 < K) pre32(wA, pk4, (kb + 64) >> 1, j);
        else             pre32(wA, pknext, 0, j);
        comp32(wB, hhb, kb + 32, a1_01, a1_23, a2_01, a2_23);
    }
}

// Block-wide sum of 8 per-thread floats (256 threads). red holds 64 floats.
__device__ __forceinline__ void block_reduce8(float v[8], float* red,
                                              int lane, int warp, float out[8]) {
#pragma unroll
    for (int off = 16; off > 0; off >>= 1) {
#pragma unroll
        for (int i = 0; i < 8; i++)
            v[i] += __shfl_xor_sync(0xffffffffu, v[i], off);
    }
    if (lane == 0) {
#pragma unroll
        for (int i = 0; i < 8; i++) red[warp * 8 + i] = v[i];
    }
    __syncthreads();
#pragma unroll
    for (int i = 0; i < 8; i++) out[i] = 0.f;
#pragma unroll
    for (int w = 0; w < 8; w++) {
#pragma unroll
        for (int i = 0; i < 8; i++) out[i] += red[w * 8 + i];
    }
    __syncthreads();
}

// RK4 + LayerNorm + tanh. One barrier per stage (double-buffered hh).
// wA: in = pk4 rows 0..31; out = pknext rows 0..31.
__device__ __forceinline__ void rk4_ln(const float4* __restrict__ pk4,
                                       const float4* __restrict__ pknext,
                                       ull (*hh2)[2 * H], float* red,
                                       int j, int lane, int warp,
                                       float h[4], const float pin[4], const float pg[4],
                                       float invtau, float lng, float lnb,
                                       float4 wA[16]) {
    float hs[4], kacc[4];
#pragma unroll
    for (int b = 0; b < 4; b++) hs[b] = h[b];

#pragma unroll 1
    for (int s = 0; s < 4; s++) {
        float cn  = (s < 2) ? 0.5f : (s == 2 ? 1.0f : 0.0f);
        float wks = (s == 1 || s == 2) ? 2.0f : 1.0f;
        ull* hhb = hh2[s & 1];
        *(ulonglong2*)&hhb[2 * j] =
            make_ulonglong2(pk2(hs[0], hs[1]), pk2(hs[2], hs[3]));
        __syncthreads();

        ull ag01 = pk2(pg[0], pg[1]), ag23 = pk2(pg[2], pg[3]);
        ull ar01 = 0ull, ar23 = 0ull;
        const float4* nxt = (s == 3) ? pknext : pk4;
        matvecP<H>(pk4, nxt, j, hhb, wA, ag01, ag23, ar01, ar23);

        float ag[4], ar[4];
        up2(ag01, ag[0], ag[1]); up2(ag23, ag[2], ag[3]);
        up2(ar01, ar[0], ar[1]); up2(ar23, ar[2], ar[3]);
#pragma unroll
        for (int b = 0; b < 4; b++) {
            float tg = fast_tanh(ag[b]);
            float g  = fast_sigmoid(tg);
            float kb = pin[b] - hs[b] * invtau + g * ar[b];
            if (s == 0) kacc[b] = kb; else kacc[b] += wks * kb;
            hs[b] = h[b] + cn * kb;
        }
    }

    float hn[4], v8[8];
#pragma unroll
    for (int b = 0; b < 4; b++) {
        hn[b]     = h[b] + kacc[b] * (1.f / 6.f);
        v8[b]     = hn[b];
        v8[4 + b] = hn[b] * hn[b];
    }
    float o8[8];
    block_reduce8(v8, red, lane, warp, o8);
#pragma unroll
    for (int b = 0; b < 4; b++) {
        float mu   = o8[b] * (1.f / (float)H);
        float var  = o8[4 + b] * (1.f / (float)H) - mu * mu;
        float rstd = rsqrtf(var + LN_EPS);
        h[b] = fast_tanh((hn[b] - mu) * rstd * lng + lnb);   // clip is a no-op
    }
}

__global__ __launch_bounds__(256)
void ltc_main(const float* __restrict__ seq,  const float* __restrict__ ctx,
              const float* __restrict__ tau0, const float* __restrict__ bg0,
              const float* __restrict__ lng0, const float* __restrict__ lnb0,
              const float* __restrict__ tau1, const float* __restrict__ bg1,
              const float* __restrict__ lng1, const float* __restrict__ lnb1,
              const float* __restrict__ cW1,  const float* __restrict__ cb1,
              const float* __restrict__ cW2,  const float* __restrict__ cb2,
              float* __restrict__ out) {
    __shared__ __align__(16) ull hh2[2][2 * H];   // stage vector, batch-paired
    __shared__ __align__(16) ull xin2[2 * H];     // layer-1 input
    __shared__ __align__(16) ull xs2[2 * FS];     // seq features at t (ctx at init)
    __shared__ float red[64];

    int j    = threadIdx.x;
    int lane = j & 31, warp = j >> 5;
    int b0   = blockIdx.x * 4;

    float invt0 = 1.f / (log1pf(expf(tau0[j])) + 1.f);
    float invt1 = 1.f / (log1pf(expf(tau1[j])) + 1.f);
    float lng0v = lng0[j], lnb0v = lnb0[j];
    float lng1v = lng1[j], lnb1v = lnb1[j];
    float rbg1  = bg1[j];

    // ---- context contributions to layer-0 pre-activations (constant over t) ----
    if (j < FC) {
        float c0 = ctx[(b0 + 0) * FC + j], c1 = ctx[(b0 + 1) * FC + j];
        float c2 = ctx[(b0 + 2) * FC + j], c3 = ctx[(b0 + 3) * FC + j];
        *(ulonglong2*)&xs2[2 * j] = make_ulonglong2(pk2(c0, c1), pk2(c2, c3));
    }
    __syncthreads();
    float cwin[4], cg[4];
    {
        float bv = bg0[j];
#pragma unroll
        for (int b = 0; b < 4; b++) { cwin[b] = 0.f; cg[b] = bv; }
    }
#pragma unroll 4
    for (int kp = 0; kp < FC / 2; kp++) {
        float4 w = g4_c0[kp * H + j];
        float x0, x1, x2, x3, y0, y1, y2, y3;
        up2(xs2[4 * kp + 0], x0, x1); up2(xs2[4 * kp + 1], x2, x3);
        up2(xs2[4 * kp + 2], y0, y1); up2(xs2[4 * kp + 3], y2, y3);
        cwin[0] += w.x * x0 + w.z * y0; cg[0] += w.y * x0 + w.w * y0;
        cwin[1] += w.x * x1 + w.z * y1; cg[1] += w.y * x1 + w.w * y1;
        cwin[2] += w.x * x2 + w.z * y2; cg[2] += w.y * x2 + w.w * y2;
        cwin[3] += w.x * x3 + w.z * y3; cg[3] += w.y * x3 + w.w * y3;
    }
    __syncthreads();   // done with ctx in xs2 before reuse for seq

    float h0r[4] = {0.f, 0.f, 0.f, 0.f};
    float h1r[4] = {0.f, 0.f, 0.f, 0.f};

    const float* seqb0 = seq + (size_t)(b0 + 0) * Tsz * FS;
    const float* seqb1 = seq + (size_t)(b0 + 1) * Tsz * FS;
    const float* seqb2 = seq + (size_t)(b0 + 2) * Tsz * FS;
    const float* seqb3 = seq + (size_t)(b0 + 3) * Tsz * FS;

    // prefetch t=0 seq features + cold-start the weight pipeline
    float sq[4] = {0.f, 0.f, 0.f, 0.f};
    if (j < FS) {
        sq[0] = seqb0[j]; sq[1] = seqb1[j]; sq[2] = seqb2[j]; sq[3] = seqb3[j];
    }
    float4 wA[16];
    pre32(wA, g4_s0, 0, j);

#pragma unroll 1
    for (int t = 0; t < Tsz; t++) {
        if (j < FS)
            *(ulonglong2*)&xs2[2 * j] =
                make_ulonglong2(pk2(sq[0], sq[1]), pk2(sq[2], sq[3]));
        __syncthreads();

        // prefetch t+1 seq features (a full timestep of latency to hide)
        if (j < FS) {
            int tn = (t + 1 < Tsz) ? t + 1 : t;
            int o  = tn * FS + j;
            sq[0] = seqb0[o]; sq[1] = seqb1[o]; sq[2] = seqb2[o]; sq[3] = seqb3[o];
        }

        // ---- layer 0 input projection (seq part; ctx folded into cwin/cg) ----
        ull p01 = pk2(cwin[0], cwin[1]), p23 = pk2(cwin[2], cwin[3]);
        ull g01 = pk2(cg[0],   cg[1]),   g23 = pk2(cg[2],   cg[3]);
        matvecP<FS>(g4_s0, g4_h0, j, xs2, wA, p01, p23, g01, g23);
        float pin[4], pg[4];
        up2(p01, pin[0], pin[1]); up2(p23, pin[2], pin[3]);
        up2(g01, pg[0],  pg[1]);  up2(g23, pg[2],  pg[3]);

        rk4_ln(g4_h0, g4_x1, hh2, red, j, lane, warp, h0r, pin, pg,
               invt0, lng0v, lnb0v, wA);

        // ---- hand layer-0 output to layer 1 ----
        *(ulonglong2*)&xin2[2 * j] =
            make_ulonglong2(pk2(h0r[0], h0r[1]), pk2(h0r[2], h0r[3]));
        __syncthreads();

        // ---- layer 1 input projection ----
        p01 = 0ull; p23 = 0ull;
        g01 = pk2(rbg1, rbg1); g23 = g01;
        matvecP<H>(g4_x1, g4_h1, j, xin2, wA, p01, p23, g01, g23);
        up2(p01, pin[0], pin[1]); up2(p23, pin[2], pin[3]);
        up2(g01, pg[0],  pg[1]);  up2(g23, pg[2],  pg[3]);

        rk4_ln(g4_h1, g4_s0, hh2, red, j, lane, warp, h1r, pin, pg,
               invt1, lng1v, lnb1v, wA);
    }

    // ---- head: out = relu(h1 @ cW1.T + cb1) @ cW2.T + cb2 ----
    *(ulonglong2*)&xin2[2 * j] =
        make_ulonglong2(pk2(h1r[0], h1r[1]), pk2(h1r[2], h1r[3]));
    __syncthreads();

    float p[4] = {0.f, 0.f, 0.f, 0.f};
    if (j < 128) {
        float acc[4];
        float bb = cb1[j];
#pragma unroll
        for (int b = 0; b < 4; b++) acc[b] = bb;
#pragma unroll 8
        for (int k = 0; k < H; k++) {
            float w = cW1[j * H + k];
            float x0, x1, x2, x3;
            up2(xin2[2 * k], x0, x1); up2(xin2[2 * k + 1], x2, x3);
            acc[0] += w * x0; acc[1] += w * x1;
            acc[2] += w * x2; acc[3] += w * x3;
        }
        float w2 = cW2[j];
#pragma unroll
        for (int b = 0; b < 4; b++) p[b] = fmaxf(acc[b], 0.f) * w2;
    }
    float v8[8], o8[8];
#pragma unroll
    for (int i = 0; i < 8; i++) v8[i] = (i < 4) ? p[i] : 0.f;
    block_reduce8(v8, red, lane, warp, o8);
    if (j < 4) out[b0 + j] = o8[j] + cb2[0];
}

extern "C" void kernel_launch(void* const* d_in, const int* in_sizes, int n_in,
                              void* d_out, int out_size) {
    const float* seq   = (const float*)d_in[0];
    const float* ctx   = (const float*)d_in[1];
    const float* tau0  = (const float*)d_in[2];
    const float* Win0  = (const float*)d_in[3];
    const float* Wrec0 = (const float*)d_in[4];
    const float* Wg0   = (const float*)d_in[5];
    const float* bg0   = (const float*)d_in[6];
    const float* lng0  = (const float*)d_in[7];
    const float* lnb0  = (const float*)d_in[8];
    const float* tau1  = (const float*)d_in[9];
    const float* Win1  = (const float*)d_in[10];
    const float* Wrec1 = (const float*)d_in[11];
    const float* Wg1   = (const float*)d_in[12];
    const float* bg1   = (const float*)d_in[13];
    const float* lng1  = (const float*)d_in[14];
    const float* lnb1  = (const float*)d_in[15];
    const float* cW1   = (const float*)d_in[16];
    const float* cb1   = (const float*)d_in[17];
    const float* cW2   = (const float*)d_in[18];
    const float* cb2   = (const float*)d_in[19];
    float* out = (float*)d_out;

    setup_kernel<<<432, 256>>>(Win0, Wrec0, Wg0, Win1, Wrec1, Wg1);
    ltc_main<<<128, 256>>>(seq, ctx, tau0, bg0, lng0, lnb0,
                           tau1, bg1, lng1, lnb1,
                           cW1, cb1, cW2, cb2, out);
}

// round 5
// speedup vs baseline: 1.4537x; 1.4537x over previous
#include <cuda_runtime.h>
#include <math.h>

#define Tsz 512
#define FS 64
#define FC 32
#define H 256
#define LN_EPS 1e-5f

typedef unsigned long long ull;

// Weights packed k-major as float4 covering TWO k-rows:
//   g4[kp*H + j] = { m1[2kp, j], m2[2kp, j], m1[2kp+1, j], m2[2kp+1, j] }
__device__ float4 g4_s0[(FS / 2) * H];   // {Win0_seq, Wg0_seq}
__device__ float4 g4_c0[(FC / 2) * H];   // {Win0_ctx, Wg0_ctx}
__device__ float4 g4_h0[(H / 2) * H];    // {Wg0_h,    Wrec0}
__device__ float4 g4_x1[(H / 2) * H];    // {Win1,     Wg1_x}
__device__ float4 g4_h1[(H / 2) * H];    // {Wg1_h,    Wrec1}

__global__ void setup_kernel(const float* __restrict__ Win0,
                             const float* __restrict__ Wrec0,
                             const float* __restrict__ Wg0,
                             const float* __restrict__ Win1,
                             const float* __restrict__ Wrec1,
                             const float* __restrict__ Wg1) {
    int j  = threadIdx.x;
    int k2 = blockIdx.x;
    if (k2 < 32) {
        int k = 2 * k2;
        g4_s0[k2 * H + j] = make_float4(Win0[j * 96 + k],     Wg0[j * 352 + k],
                                        Win0[j * 96 + k + 1], Wg0[j * 352 + k + 1]);
    } else if (k2 < 48) {
        int kk = 2 * (k2 - 32);
        g4_c0[(k2 - 32) * H + j] =
            make_float4(Win0[j * 96 + 64 + kk],     Wg0[j * 352 + 64 + kk],
                        Win0[j * 96 + 64 + kk + 1], Wg0[j * 352 + 64 + kk + 1]);
    } else if (k2 < 176) {
        int kk = 2 * (k2 - 48);
        g4_h0[(k2 - 48) * H + j] =
            make_float4(Wg0[j * 352 + 96 + kk],     Wrec0[j * H + kk],
                        Wg0[j * 352 + 96 + kk + 1], Wrec0[j * H + kk + 1]);
    } else if (k2 < 304) {
        int kk = 2 * (k2 - 176);
        g4_x1[(k2 - 176) * H + j] =
            make_float4(Win1[j * H + kk],     Wg1[j * 512 + kk],
                        Win1[j * H + kk + 1], Wg1[j * 512 + kk + 1]);
    } else {
        int kk = 2 * (k2 - 304);
        g4_h1[(k2 - 304) * H + j] =
            make_float4(Wg1[j * 512 + 256 + kk],     Wrec1[j * H + kk],
                        Wg1[j * 512 + 256 + kk + 1], Wrec1[j * H + kk + 1]);
    }
}

// ---- packed fp32x2 helpers ----
__device__ __forceinline__ ull pk2(float a, float b) {
    ull r; asm("mov.b64 %0,{%1,%2};" : "=l"(r) : "f"(a), "f"(b)); return r;
}
__device__ __forceinline__ void up2(ull v, float& a, float& b) {
    asm("mov.b64 {%0,%1},%2;" : "=f"(a), "=f"(b) : "l"(v));
}
__device__ __forceinline__ void fma2(ull& d, ull a, ull b) {
    asm("fma.rn.f32x2 %0,%1,%2,%0;" : "+l"(d) : "l"(a), "l"(b));
}
__device__ __forceinline__ ull add2(ull a, ull b) {
    ull r; asm("add.rn.f32x2 %0,%1,%2;" : "=l"(r) : "l"(a), "l"(b)); return r;
}

// ---- fast transcendentals (abs err ~1e-7; threshold is 1e-3) ----
__device__ __forceinline__ float fast_tanh(float x) {
    float xc = fminf(fmaxf(x, -15.f), 15.f);
    float e  = __expf(2.f * xc);
    return __fdividef(e - 1.f, e + 1.f);
}
__device__ __forceinline__ float fast_sigmoid(float x) {
    return __fdividef(1.f, 1.f + __expf(-x));
}

// ---- 16-k-row block: 8x LDG.128 preload, dual-matvec compute ----
__device__ __forceinline__ void pre8(float4 w[8], const float4* __restrict__ pk4,
                                     int kp, int j) {
#pragma unroll
    for (int i = 0; i < 8; i++) w[i] = pk4[(size_t)(kp + i) * H + j];
}

__device__ __forceinline__ void comp8(const float4 w[8], const ull* __restrict__ hhb,
                                      int rb,
                                      ull& a1_01, ull& a1_23, ull& a2_01, ull& a2_23) {
#pragma unroll
    for (int i = 0; i < 8; i++) {
        ulonglong2 hA = *(const ulonglong2*)(hhb + 2 * (size_t)(rb + 2 * i));
        ulonglong2 hB = *(const ulonglong2*)(hhb + 2 * (size_t)(rb + 2 * i + 1));
        ull wx0 = pk2(w[i].x, w[i].x), wy0 = pk2(w[i].y, w[i].y);
        fma2(a1_01, wx0, hA.x); fma2(a1_23, wx0, hA.y);
        fma2(a2_01, wy0, hA.x); fma2(a2_23, wy0, hA.y);
        ull wx1 = pk2(w[i].z, w[i].z), wy1 = pk2(w[i].w, w[i].w);
        fma2(a1_01, wx1, hB.x); fma2(a1_23, wx1, hB.y);
        fma2(a2_01, wy1, hB.x); fma2(a2_23, wy1, hB.y);
    }
}

// Pipelined dual matvec over NBLK 16-row blocks starting at kp = kpbase.
// On entry wA must hold block 0 (preloaded earlier, behind a barrier).
template<int NBLK>
__device__ __forceinline__ void matvecS(const float4* __restrict__ pk4, int j,
                                        int kpbase, const ull* __restrict__ hhb,
                                        float4 wA[8],
                                        ull& a1_01, ull& a1_23, ull& a2_01, ull& a2_23) {
    float4 wB[8];
#pragma unroll 1
    for (int b = 0; b < NBLK; b += 2) {
        pre8(wB, pk4, kpbase + (b + 1) * 8, j);
        comp8(wA, hhb, (kpbase + b * 8) * 2, a1_01, a1_23, a2_01, a2_23);
        if (b + 2 < NBLK) pre8(wA, pk4, kpbase + (b + 2) * 8, j);
        comp8(wB, hhb, (kpbase + (b + 1) * 8) * 2, a1_01, a1_23, a2_01, a2_23);
    }
}

// Block-wide sum of 8 per-thread floats over 512 threads (16 warps).
__device__ __forceinline__ void block_reduce8(float v[8], float* red,
                                              int lane, int warp, float out[8]) {
#pragma unroll
    for (int off = 16; off > 0; off >>= 1) {
#pragma unroll
        for (int i = 0; i < 8; i++)
            v[i] += __shfl_xor_sync(0xffffffffu, v[i], off);
    }
    if (lane == 0) {
#pragma unroll
        for (int i = 0; i < 8; i++) red[warp * 8 + i] = v[i];
    }
    __syncthreads();
#pragma unroll
    for (int i = 0; i < 8; i++) out[i] = 0.f;
#pragma unroll
    for (int w = 0; w < 16; w++) {
#pragma unroll
        for (int i = 0; i < 8; i++) out[i] += red[w * 8 + i];
    }
    __syncthreads();
}

// RK4 + LayerNorm + tanh, k-split across two thread-halves.
// Entry: hh2[0] holds current h (written by half 0), wA holds pk4 block 0,
// no barrier issued yet. Exit: h updated (half 0 only), wA holds pknext blk 0.
__device__ __forceinline__ void rk4_ln(const float4* __restrict__ pk4, int kpbase,
                                       const float4* __restrict__ pknext, int kpnext,
                                       ull (*hh2)[2 * H], ull (*part)[256], float* red,
                                       int jj, int half, int lane, int warp,
                                       float h[4], const float pin[4], const float pg[4],
                                       float invtau, float lng, float lnb,
                                       float4 wA[8]) {
    float hs[4], kacc[4], hn[4];
#pragma unroll
    for (int b = 0; b < 4; b++) hs[b] = h[b];

#pragma unroll 1
    for (int s = 0; s < 4; s++) {
        __syncthreads();   // syncA: hh2[s&1] + wA ready
        ull ag01, ag23, ar01 = 0ull, ar23 = 0ull;
        if (half == 0) { ag01 = pk2(pg[0], pg[1]); ag23 = pk2(pg[2], pg[3]); }
        else           { ag01 = 0ull;              ag23 = 0ull; }
        matvecS<8>(pk4, jj, kpbase, hh2[s & 1], wA, ag01, ag23, ar01, ar23);
        if (half == 1) {
            part[0][jj] = ag01; part[1][jj] = ag23;
            part[2][jj] = ar01; part[3][jj] = ar23;
        }
        __syncthreads();   // syncB: partials visible
        if (s < 3) pre8(wA, pk4, kpbase, jj);
        else       pre8(wA, pknext, kpnext, jj);
        if (half == 0) {
            ag01 = add2(ag01, part[0][jj]); ag23 = add2(ag23, part[1][jj]);
            ar01 = add2(ar01, part[2][jj]); ar23 = add2(ar23, part[3][jj]);
            float ag[4], ar[4];
            up2(ag01, ag[0], ag[1]); up2(ag23, ag[2], ag[3]);
            up2(ar01, ar[0], ar[1]); up2(ar23, ar[2], ar[3]);
            float cn  = (s < 2) ? 0.5f : 1.0f;
            float wks = (s == 1 || s == 2) ? 2.0f : 1.0f;
#pragma unroll
            for (int b = 0; b < 4; b++) {
                float tg = fast_tanh(ag[b]);
                float g  = fast_sigmoid(tg);
                float kb = pin[b] - hs[b] * invtau + g * ar[b];
                if (s == 0) kacc[b] = kb; else kacc[b] += wks * kb;
                if (s < 3) hs[b] = h[b] + cn * kb;
            }
            if (s < 3)
                *(ulonglong2*)&hh2[(s + 1) & 1][2 * jj] =
                    make_ulonglong2(pk2(hs[0], hs[1]), pk2(hs[2], hs[3]));
        }
    }

    float v8[8];
    if (half == 0) {
#pragma unroll
        for (int b = 0; b < 4; b++) {
            hn[b]     = h[b] + kacc[b] * (1.f / 6.f);
            v8[b]     = hn[b];
            v8[4 + b] = hn[b] * hn[b];
        }
    } else {
#pragma unroll
        for (int i = 0; i < 8; i++) v8[i] = 0.f;
    }
    float o8[8];
    block_reduce8(v8, red, lane, warp, o8);
    if (half == 0) {
#pragma unroll
        for (int b = 0; b < 4; b++) {
            float mu   = o8[b] * (1.f / (float)H);
            float var  = o8[4 + b] * (1.f / (float)H) - mu * mu;
            float rstd = rsqrtf(var + LN_EPS);
            h[b] = fast_tanh((hn[b] - mu) * rstd * lng + lnb);   // clip is a no-op
        }
    }
}

__global__ __launch_bounds__(512, 1)
void ltc_main(const float* __restrict__ seq,  const float* __restrict__ ctx,
              const float* __restrict__ tau0, const float* __restrict__ bg0,
              const float* __restrict__ lng0, const float* __restrict__ lnb0,
              const float* __restrict__ tau1, const float* __restrict__ bg1,
              const float* __restrict__ lng1, const float* __restrict__ lnb1,
              const float* __restrict__ cW1,  const float* __restrict__ cb1,
              const float* __restrict__ cW2,  const float* __restrict__ cb2,
              float* __restrict__ out) {
    __shared__ __align__(16) ull hh2[2][2 * H];   // stage vector, batch-paired
    __shared__ __align__(16) ull xin2[2 * H];     // layer-1 input
    __shared__ __align__(16) ull xs2[2 * FS];     // seq features at t
    __shared__ __align__(16) ull part[4][256];    // cross-half partial sums
    __shared__ __align__(16) ull cwg[4][256];     // ctx-folded {cwin, cg} packed
    __shared__ float red[128];

    int tid  = threadIdx.x;
    int jj   = tid & 255;          // neuron
    int half = tid >> 8;           // k-half
    int lane = tid & 31, warp = tid >> 5;
    int b0   = blockIdx.x * 4;

    float invt0 = 1.f / (log1pf(expf(tau0[jj])) + 1.f);
    float invt1 = 1.f / (log1pf(expf(tau1[jj])) + 1.f);
    float lng0v = lng0[jj], lnb0v = lnb0[jj];
    float lng1v = lng1[jj], lnb1v = lnb1[jj];
    float rbg1  = bg1[jj];

    // ---- ctx contributions to layer-0 pre-activations (constant over t) ----
    if (tid < FC) {
        float c0 = ctx[(b0 + 0) * FC + tid], c1 = ctx[(b0 + 1) * FC + tid];
        float c2 = ctx[(b0 + 2) * FC + tid], c3 = ctx[(b0 + 3) * FC + tid];
        *(ulonglong2*)&xs2[2 * tid] = make_ulonglong2(pk2(c0, c1), pk2(c2, c3));
    }
    __syncthreads();
    if (half == 0) {
        float cw[4], cg[4];
        float bv = bg0[jj];
#pragma unroll
        for (int b = 0; b < 4; b++) { cw[b] = 0.f; cg[b] = bv; }
#pragma unroll 4
        for (int kp = 0; kp < FC / 2; kp++) {
            float4 w = g4_c0[kp * H + jj];
            float x0, x1, x2, x3, y0, y1, y2, y3;
            up2(xs2[4 * kp + 0], x0, x1); up2(xs2[4 * kp + 1], x2, x3);
            up2(xs2[4 * kp + 2], y0, y1); up2(xs2[4 * kp + 3], y2, y3);
            cw[0] += w.x * x0 + w.z * y0; cg[0] += w.y * x0 + w.w * y0;
            cw[1] += w.x * x1 + w.z * y1; cg[1] += w.y * x1 + w.w * y1;
            cw[2] += w.x * x2 + w.z * y2; cg[2] += w.y * x2 + w.w * y2;
            cw[3] += w.x * x3 + w.z * y3; cg[3] += w.y * x3 + w.w * y3;
        }
        cwg[0][jj] = pk2(cw[0], cw[1]); cwg[1][jj] = pk2(cw[2], cw[3]);
        cwg[2][jj] = pk2(cg[0], cg[1]); cwg[3][jj] = pk2(cg[2], cg[3]);
    }
    __syncthreads();

    float h0r[4] = {0.f, 0.f, 0.f, 0.f};
    float h1r[4] = {0.f, 0.f, 0.f, 0.f};

    const int kpS = half * 16;   // proj0: FS=64 rows -> 32 kp, half = 16 kp
    const int kpH = half * 64;   // H matvecs: 256 rows -> 128 kp, half = 64 kp

    float4 wA[8];
    pre8(wA, g4_s0, kpS, jj);

#pragma unroll 1
    for (int t = 0; t < Tsz; t++) {
        // seq features for this t (DRAM-streamed; exposure ~600cyc/t, negligible)
        if (tid < FS) {
            size_t o = (size_t)t * FS + tid;
            float s0v = seq[(size_t)(b0 + 0) * Tsz * FS + o];
            float s1v = seq[(size_t)(b0 + 1) * Tsz * FS + o];
            float s2v = seq[(size_t)(b0 + 2) * Tsz * FS + o];
            float s3v = seq[(size_t)(b0 + 3) * Tsz * FS + o];
            *(ulonglong2*)&xs2[2 * tid] =
                make_ulonglong2(pk2(s0v, s1v), pk2(s2v, s3v));
        }
        __syncthreads();   // syncA for proj0 (xs2 + wA ready)

        // ---- layer 0 input projection (seq part; ctx folded in cwg) ----
        ull p01, p23, g01, g23;
        if (half == 0) { p01 = cwg[0][jj]; p23 = cwg[1][jj];
                         g01 = cwg[2][jj]; g23 = cwg[3][jj]; }
        else           { p01 = 0ull; p23 = 0ull; g01 = 0ull; g23 = 0ull; }
        matvecS<2>(g4_s0, jj, kpS, xs2, wA, p01, p23, g01, g23);
        if (half == 1) {
            part[0][jj] = p01; part[1][jj] = p23;
            part[2][jj] = g01; part[3][jj] = g23;
        }
        __syncthreads();   // syncB
        pre8(wA, g4_h0, kpH, jj);
        float pin[4], pg[4];
        if (half == 0) {
            p01 = add2(p01, part[0][jj]); p23 = add2(p23, part[1][jj]);
            g01 = add2(g01, part[2][jj]); g23 = add2(g23, part[3][jj]);
            up2(p01, pin[0], pin[1]); up2(p23, pin[2], pin[3]);
            up2(g01, pg[0],  pg[1]);  up2(g23, pg[2],  pg[3]);
            *(ulonglong2*)&hh2[0][2 * jj] =
                make_ulonglong2(pk2(h0r[0], h0r[1]), pk2(h0r[2], h0r[3]));
        }
        rk4_ln(g4_h0, kpH, g4_x1, kpH, hh2, part, red, jj, half, lane, warp,
               h0r, pin, pg, invt0, lng0v, lnb0v, wA);

        // ---- hand layer-0 output to layer 1 ----
        if (half == 0)
            *(ulonglong2*)&xin2[2 * jj] =
                make_ulonglong2(pk2(h0r[0], h0r[1]), pk2(h0r[2], h0r[3]));
        __syncthreads();   // syncA for proj1 (xin2 + wA=g4_x1 blk0 ready)

        // ---- layer 1 input projection ----
        if (half == 0) { p01 = 0ull; p23 = 0ull;
                         g01 = pk2(rbg1, rbg1); g23 = g01; }
        else           { p01 = 0ull; p23 = 0ull; g01 = 0ull; g23 = 0ull; }
        matvecS<8>(g4_x1, jj, kpH, xin2, wA, p01, p23, g01, g23);
        if (half == 1) {
            part[0][jj] = p01; part[1][jj] = p23;
            part[2][jj] = g01; part[3][jj] = g23;
        }
        __syncthreads();   // syncB
        pre8(wA, g4_h1, kpH, jj);
        if (half == 0) {
            p01 = add2(p01, part[0][jj]); p23 = add2(p23, part[1][jj]);
            g01 = add2(g01, part[2][jj]); g23 = add2(g23, part[3][jj]);
            up2(p01, pin[0], pin[1]); up2(p23, pin[2], pin[3]);
            up2(g01, pg[0],  pg[1]);  up2(g23, pg[2],  pg[3]);
            *(ulonglong2*)&hh2[0][2 * jj] =
                make_ulonglong2(pk2(h1r[0], h1r[1]), pk2(h1r[2], h1r[3]));
        }
        rk4_ln(g4_h1, kpH, g4_s0, kpS, hh2, part, red, jj, half, lane, warp,
               h1r, pin, pg, invt1, lng1v, lnb1v, wA);
    }

    // ---- head: out = relu(h1 @ cW1.T + cb1) @ cW2.T + cb2 ----
    if (half == 0)
        *(ulonglong2*)&xin2[2 * jj] =
            make_ulonglong2(pk2(h1r[0], h1r[1]), pk2(h1r[2], h1r[3]));
    __syncthreads();

    float p[4] = {0.f, 0.f, 0.f, 0.f};
    if (tid < 128) {
        float acc[4];
        float bb = cb1[tid];
#pragma unroll
        for (int b = 0; b < 4; b++) acc[b] = bb;
#pragma unroll 8
        for (int k = 0; k < H; k++) {
            float w = cW1[tid * H + k];
            float x0, x1, x2, x3;
            up2(xin2[2 * k], x0, x1); up2(xin2[2 * k + 1], x2, x3);
            acc[0] += w * x0; acc[1] += w * x1;
            acc[2] += w * x2; acc[3] += w * x3;
        }
        float w2 = cW2[tid];
#pragma unroll
        for (int b = 0; b < 4; b++) p[b] = fmaxf(acc[b], 0.f) * w2;
    }
    float v8[8], o8[8];
#pragma unroll
    for (int i = 0; i < 8; i++) v8[i] = (i < 4) ? p[i] : 0.f;
    block_reduce8(v8, red, lane, warp, o8);
    if (tid < 4) out[b0 + tid] = o8[tid] + cb2[0];
}

extern "C" void kernel_launch(void* const* d_in, const int* in_sizes, int n_in,
                              void* d_out, int out_size) {
    const float* seq   = (const float*)d_in[0];
    const float* ctx   = (const float*)d_in[1];
    const float* tau0  = (const float*)d_in[2];
    const float* Win0  = (const float*)d_in[3];
    const float* Wrec0 = (const float*)d_in[4];
    const float* Wg0   = (const float*)d_in[5];
    const float* bg0   = (const float*)d_in[6];
    const float* lng0  = (const float*)d_in[7];
    const float* lnb0  = (const float*)d_in[8];
    const float* tau1  = (const float*)d_in[9];
    const float* Win1  = (const float*)d_in[10];
    const float* Wrec1 = (const float*)d_in[11];
    const float* Wg1   = (const float*)d_in[12];
    const float* bg1   = (const float*)d_in[13];
    const float* lng1  = (const float*)d_in[14];
    const float* lnb1  = (const float*)d_in[15];
    const float* cW1   = (const float*)d_in[16];
    const float* cb1   = (const float*)d_in[17];
    const float* cW2   = (const float*)d_in[18];
    const float* cb2   = (const float*)d_in[19];
    float* out = (float*)d_out;

    setup_kernel<<<432, 256>>>(Win0, Wrec0, Wg0, Win1, Wrec1, Wg1);
    ltc_main<<<128, 512>>>(seq, ctx, tau0, bg0, lng0, lnb0,
                           tau1, bg1, lng1, lnb1,
                           cW1, cb1, cW2, cb2, out);
}